// round 15
// baseline (speedup 1.0000x reference)
#include <cuda_runtime.h>
#include <cuda_bf16.h>

#define N_NODES 50000
#define N_EDGES 500000
#define H 128
#define G_GRAPHS 100
#define NPG 500
#define NPROT 400
#define PN 35
#define LN 11
#define NLAYERS 4
#define EPS 1e-5f

// ---------------- scratch ----------------
__device__ float g_h[N_NODES * H];
__device__ float g_P1[N_NODES * H];
__device__ float g_P2[N_NODES * H];
__device__ float g_agg[N_NODES * H];
__device__ float g_pos[N_NODES * 3];
__device__ float g_posdelta[N_NODES * 3];
__device__ float g_deg[N_NODES];
__device__ float g_bnstats[2 * H];
__device__ int g_rowcur[N_NODES];
__device__ int g_srow[N_EDGES];
__device__ int g_scol[N_EDGES];
__device__ int g_sperm[N_EDGES];
__device__ int g_flag;
// pre-packed bf16 hi/lo weight fragments
__device__ unsigned g_pk_proj[NLAYERS * 32768];  // hi 16384 | lo 16384
__device__ unsigned g_pk_w2[NLAYERS * 16384];    // hi 8192 | lo 8192
__device__ unsigned g_pk_c1[NLAYERS * 16384];
__device__ unsigned g_pk_n1[NLAYERS * 32768];    // [half0: hi|lo][half1: hi|lo]
__device__ unsigned g_pk_n2[NLAYERS * 16384];

__device__ __forceinline__ float silu_f(float x) {
    return x / (1.f + __expf(-x));
}

// ---- bf16 m16n8k16 mma ----
__device__ __forceinline__ void mma_bf16(float* c, const uint4& a, const uint2& b) {
    asm volatile(
        "mma.sync.aligned.m16n8k16.row.col.f32.bf16.bf16.f32 "
        "{%0,%1,%2,%3}, {%4,%5,%6,%7}, {%8,%9}, {%0,%1,%2,%3};"
        : "+f"(c[0]), "+f"(c[1]), "+f"(c[2]), "+f"(c[3])
        : "r"(a.x), "r"(a.y), "r"(a.z), "r"(a.w), "r"(b.x), "r"(b.y));
}
__device__ __forceinline__ unsigned split2(float v0, float v1, unsigned& lo) {
    __nv_bfloat16 h0 = __float2bfloat16(v0);
    __nv_bfloat16 h1 = __float2bfloat16(v1);
    __nv_bfloat16 l0 = __float2bfloat16(v0 - __bfloat162float(h0));
    __nv_bfloat16 l1 = __float2bfloat16(v1 - __bfloat162float(h1));
    lo = (unsigned)__bfloat16_as_ushort(l0) | ((unsigned)__bfloat16_as_ushort(l1) << 16);
    return (unsigned)__bfloat16_as_ushort(h0) | ((unsigned)__bfloat16_as_ushort(h1) << 16);
}
__device__ __forceinline__ void mma3(float* c, const uint4& ah, const uint4& al,
                                     const uint2& bh, const uint2& bl) {
    mma_bf16(c, ah, bh);
    mma_bf16(c, ah, bl);
    mma_bf16(c, al, bh);
}
__device__ __forceinline__ int fragAb(int e, int j0, int KT) {
    int jin = j0 & 15;
    int tid = (jin & 7) >> 1;
    int reg = ((jin >> 3) << 1) | ((e >> 3) & 1);
    int lane = ((e & 7) << 2) | tid;
    return (((e >> 4) * KT + (j0 >> 4)) << 7) + (lane << 2) + reg;
}
__device__ __forceinline__ float bfsum(unsigned hi, unsigned lo) {
    return __bfloat162float(__ushort_as_bfloat16((unsigned short)(hi & 0xffffu)))
         + __bfloat162float(__ushort_as_bfloat16((unsigned short)(lo & 0xffffu)));
}
#define BARH(hid) asm volatile("bar.sync %0, %1;" :: "r"((hid) + 1), "r"(512) : "memory")

// ---------------- K1: embed (also zeroes flag/deg/bnstats, copies pos) ----------------
__global__ void k_embed(const float* __restrict__ x, const float* __restrict__ pos_in,
                        const float* __restrict__ Wp, const float* __restrict__ bp,
                        const float* __restrict__ Wl, const float* __restrict__ bl) {
    __shared__ float xs[PN];
    const int i = blockIdx.x;
    const int t = threadIdx.x;
    if (t < PN) xs[t] = x[i * PN + t];
    if (t == 0) g_deg[i] = 0.f;
    if (t < 3) g_pos[i * 3 + t] = pos_in[i * 3 + t];
    if (i == 0 && t < H) { g_bnstats[t] = 0.f; g_bnstats[H + t] = 0.f; }
    if (i == 0 && t == 0) g_flag = 0;
    __syncthreads();
    const bool isp = (i % NPG) < NPROT;
    const float* W = isp ? Wp : Wl;
    const float* b = isp ? bp : bl;
    const int nk = isp ? PN : LN;
    float acc = b[t];
    for (int k = 0; k < nk; k++) acc += xs[k] * W[k * H + t];
    g_h[i * H + t] = acc;
}

// ---------------- K2: prep = bnstats + deg + weight pack ----------------
#define DEG_BLOCKS ((N_EDGES + 511) / 512)
#define PACK_PER_LAYER (16384 + 8192 + 8192 + 16384 + 8192)  // 57344
#define PACK_ITEMS (NLAYERS * PACK_PER_LAYER)
#define PACK_BLOCKS ((PACK_ITEMS + 511) / 512)
__global__ __launch_bounds__(512) void k_prep(const int* __restrict__ ei,
                                              const float* __restrict__ ew1,
                                              const float* __restrict__ ew2,
                                              const float* __restrict__ cw1,
                                              const float* __restrict__ nw1,
                                              const float* __restrict__ nw2) {
    const int t = threadIdx.x;
    if (blockIdx.x < 256) {
        const int j = t & 127;
        const int g2 = t >> 7;
        float s = 0.f, s2 = 0.f;
        for (int i = blockIdx.x * 4 + g2; i < N_NODES; i += 1024) {
            float v = g_h[i * H + j];
            s += v; s2 += v * v;
        }
        atomicAdd(&g_bnstats[j], s);
        atomicAdd(&g_bnstats[H + j], s2);
        return;
    }
    if (blockIdx.x < 256 + DEG_BLOCKS) {
        const int e = (blockIdx.x - 256) * 512 + t;
        if (e < N_EDGES) atomicAdd(&g_deg[ei[e]], 1.0f);
        return;
    }
    int idx = (blockIdx.x - 256 - DEG_BLOCKS) * 512 + t;
    if (idx >= PACK_ITEMS) return;
    int l = idx / PACK_PER_LAYER;
    int o = idx - l * PACK_PER_LAYER;
    float w0, w1;
    unsigned* hip;
    unsigned* lop;
    if (o < 16384) {            // proj
        int i = o;
        int rb = i & 1, lane = (i >> 1) & 31, kt = (i >> 6) & 7, nt = i >> 9;
        int tid = lane & 3, g = lane >> 2;
        int k0 = kt * 16 + tid * 2 + rb * 8;
        int jj = nt * 8 + g;
        const float* W = ew1 + l * 261 * H;
        int srcrow = (jj < 128) ? k0 : (128 + k0);
        int col = jj & 127;
        w0 = W[srcrow * H + col];
        w1 = W[(srcrow + 1) * H + col];
        hip = g_pk_proj + l * 32768 + i;
        lop = hip + 16384;
    } else if (o < 24576) {     // w2
        int i = o - 16384;
        int rb = i & 1, lane = (i >> 1) & 31, kt = (i >> 6) & 7, nt = i >> 9;
        int tid = lane & 3, g = lane >> 2;
        int k0 = kt * 16 + tid * 2 + rb * 8;
        int n = nt * 8 + g;
        const float* W = ew2 + l * H * H;
        w0 = W[k0 * H + n];
        w1 = W[(k0 + 1) * H + n];
        hip = g_pk_w2 + l * 16384 + i;
        lop = hip + 8192;
    } else if (o < 32768) {     // c1
        int i = o - 24576;
        int rb = i & 1, lane = (i >> 1) & 31, kt = (i >> 6) & 7, nt = i >> 9;
        int tid = lane & 3, g = lane >> 2;
        int k0 = kt * 16 + tid * 2 + rb * 8;
        int n = nt * 8 + g;
        const float* W = cw1 + l * H * H;
        w0 = W[k0 * H + n];
        w1 = W[(k0 + 1) * H + n];
        hip = g_pk_c1 + l * 16384 + i;
        lop = hip + 8192;
    } else if (o < 49152) {     // n1
        int i2 = o - 32768;
        int hk = i2 >> 13;
        int i = i2 & 8191;
        int rb = i & 1, lane = (i >> 1) & 31, kt = (i >> 6) & 7, nt = i >> 9;
        int tid = lane & 3, g = lane >> 2;
        int k0 = hk * 128 + kt * 16 + tid * 2 + rb * 8;
        int n = nt * 8 + g;
        const float* W = nw1 + l * 2 * H * H;
        w0 = W[k0 * H + n];
        w1 = W[(k0 + 1) * H + n];
        hip = g_pk_n1 + l * 32768 + hk * 16384 + i;
        lop = hip + 8192;
    } else {                    // n2
        int i = o - 49152;
        int rb = i & 1, lane = (i >> 1) & 31, kt = (i >> 6) & 7, nt = i >> 9;
        int tid = lane & 3, g = lane >> 2;
        int k0 = kt * 16 + tid * 2 + rb * 8;
        int n = nt * 8 + g;
        const float* W = nw2 + l * H * H;
        w0 = W[k0 * H + n];
        w1 = W[(k0 + 1) * H + n];
        hip = g_pk_n2 + l * 16384 + i;
        lop = hip + 8192;
    }
    unsigned lo;
    unsigned hi = split2(w0, w1, lo);
    *hip = hi;
    *lop = lo;
}

// ---------------- K3: scan(block 0) + perm(spin on flag) + proj0+BN ----------------
#define NB64 ((N_NODES + 63) / 64)
#define PERM_BLOCKS ((N_EDGES + 1023) / 1024)   // 489
__global__ __launch_bounds__(1024, 1) void k_proj0(const int* __restrict__ ei,
                                                   const float* __restrict__ b1,
                                                   const float* __restrict__ gamma,
                                                   const float* __restrict__ beta) {
    extern __shared__ float sm[];
    const int t = threadIdx.x;
    if (blockIdx.x == 0) {
        // degree exclusive scan -> g_rowcur, then publish flag
        int* sums = (int*)sm;
        const int chunk = 49;   // 49*1024 >= 50000
        int base = t * chunk;
        int lim = min(base + chunk, N_NODES);
        int s = 0;
        for (int i = base; i < lim; i++) s += (int)g_deg[i];
        sums[t] = s;
        __syncthreads();
        for (int off = 1; off < 1024; off <<= 1) {
            int v = (t >= off) ? sums[t - off] : 0;
            __syncthreads();
            sums[t] += v;
            __syncthreads();
        }
        int run = (t == 0) ? 0 : sums[t - 1];
        for (int i = base; i < lim; i++) {
            g_rowcur[i] = run;
            run += (int)g_deg[i];
        }
        __threadfence();
        __syncthreads();
        if (t == 0) atomicExch(&g_flag, 1);
        return;
    }
    if (blockIdx.x <= PERM_BLOCKS) {
        // counting-sort permutation (waits for scan flag)
        if (t == 0) {
            while (atomicAdd(&g_flag, 0) == 0) __nanosleep(64);
        }
        __syncthreads();
        int e = (blockIdx.x - 1) * 1024 + t;
        if (e < N_EDGES) {
            int r = ei[e];
            int p = atomicAdd(&g_rowcur[r], 1);
            g_srow[p] = r;
            g_scol[p] = ei[N_EDGES + e];
            g_sperm[p] = e;
        }
        return;
    }

    unsigned* wF = (unsigned*)sm;       // 32768
    unsigned* aH = wF + 32768;          // 4096
    unsigned* aL = aH + 4096;           // 4096
    const int n0 = (blockIdx.x - 1 - PERM_BLOCKS) * 64;

    {
        const uint4* s = (const uint4*)(g_pk_proj);
        uint4* d = (uint4*)wF;
        for (int i = t; i < 8192; i += 1024) d[i] = s[i];
    }
    const float inv_n = 1.f / (float)N_NODES;
    for (int i = t; i < 4096; i += 1024) {
        int n = i >> 6, jp = i & 63;
        int j0 = jp * 2;
        int gi = n0 + n;
        float2 v = make_float2(0.f, 0.f);
        if (gi < N_NODES) {
            v = *(const float2*)&g_h[gi * H + j0];
            float mu0 = g_bnstats[j0] * inv_n;
            float mu1 = g_bnstats[j0 + 1] * inv_n;
            float var0 = g_bnstats[H + j0] * inv_n - mu0 * mu0;
            float var1 = g_bnstats[H + j0 + 1] * inv_n - mu1 * mu1;
            v.x = (v.x - mu0) * rsqrtf(var0 + EPS) * gamma[j0] + beta[j0];
            v.y = (v.y - mu1) * rsqrtf(var1 + EPS) * gamma[j0 + 1] + beta[j0 + 1];
            *(float2*)&g_h[gi * H + j0] = v;   // store normalized h
        }
        unsigned lo;
        unsigned hi = split2(v.x, v.y, lo);
        int fi = fragAb(n, j0, 8);
        aH[fi] = hi;
        aL[fi] = lo;
    }
    {
        const float4 z4 = make_float4(0.f, 0.f, 0.f, 0.f);
        for (int i = t; i < 2048; i += 1024) {
            int gi = n0 + (i >> 5);
            if (gi < N_NODES) *(float4*)&g_agg[gi * H + (i & 31) * 4] = z4;
        }
    }
    if (t < 192) {
        int gi = n0 + t / 3;
        if (gi < N_NODES) g_posdelta[gi * 3 + t % 3] = 0.f;
    }
    __syncthreads();

    const int wid = t >> 5, lane = t & 31;
    const int mt = wid >> 3;
    const int ng = wid & 7;
    const int grp = lane >> 2, thr = lane & 3;
    float c[4][4];
#pragma unroll
    for (int q = 0; q < 4; q++)
#pragma unroll
        for (int r = 0; r < 4; r++) c[q][r] = 0.f;

#pragma unroll
    for (int kt = 0; kt < 8; kt++) {
        int aoff = (((mt * 8 + kt) << 5) + lane) << 2;
        uint4 ah = *(const uint4*)&aH[aoff];
        uint4 al = *(const uint4*)&aL[aoff];
#pragma unroll
        for (int q = 0; q < 4; q++) {
            int nt = ng * 4 + q;
            int bi = (((nt * 8 + kt) << 5) + lane) << 1;
            uint2 bh = *(const uint2*)&wF[bi];
            uint2 bl = *(const uint2*)&wF[16384 + bi];
            mma3(c[q], ah, al, bh, bl);
        }
    }

    const int ee0 = mt * 16 + grp, ee1 = ee0 + 8;
    const int g0 = n0 + ee0, g1 = n0 + ee1;
#pragma unroll
    for (int q = 0; q < 4; q++) {
        int nt = ng * 4 + q;
        int jj0 = nt * 8 + 2 * thr;
        int half = jj0 >> 7;
        int j = jj0 & 127;
        float* outp = half ? g_P2 : g_P1;
        float bb0 = half ? 0.f : __ldg(&b1[j]);
        float bb1 = half ? 0.f : __ldg(&b1[j + 1]);
        if (g0 < N_NODES)
            *(float2*)&outp[g0 * H + j] = make_float2(c[q][0] + bb0, c[q][1] + bb1);
        if (g1 < N_NODES)
            *(float2*)&outp[g1 * H + j] = make_float2(c[q][2] + bb0, c[q][3] + bb1);
    }
}

// ---------------- fused edge kernel: two 512-thread pipelines ----------------
__global__ __launch_bounds__(1024, 1) void k_edge(
    const float* __restrict__ eattr, int l,
    const float* __restrict__ b2, const float* __restrict__ cb1,
    const float* __restrict__ cw2, const float* __restrict__ ew1) {
    extern __shared__ float sm[];
    unsigned* w2F = (unsigned*)sm;       // 16384
    unsigned* c1F = w2F + 16384;         // 16384
    unsigned* actH = c1F + 16384;        // 8192 (two halves of 4096)
    unsigned* actL = actH + 8192;        // 8192
    float* b2_s  = (float*)(actL + 8192);  // 128
    float* cb1_s = b2_s + 128;           // 128
    float* c2_s  = cb1_s + 128;          // 128
    float* wd2_s = c2_s + 128;           // 128
    float* wea_s = wd2_s + 128;          // 512
    float* d2_s  = wea_s + 512;          // 128
    float* rel_s = d2_s + 128;           // 384
    float* ea_s  = rel_s + 384;          // 512
    float* wsum_s = ea_s + 512;          // 128
    int* row_s = (int*)(wsum_s + 128);   // 128
    int* col_s = row_s + 128;            // 128

    const int t = threadIdx.x;
    {
        const uint4* s2 = (const uint4*)(g_pk_w2 + l * 16384);
        const uint4* s1 = (const uint4*)(g_pk_c1 + l * 16384);
        uint4* d2 = (uint4*)w2F;
        uint4* d1 = (uint4*)c1F;
        for (int i = t; i < 4096; i += 1024) { d2[i] = s2[i]; d1[i] = s1[i]; }
    }
    if (t < 128) {
        b2_s[t] = b2[t]; cb1_s[t] = cb1[t]; c2_s[t] = cw2[t];
        wd2_s[t] = ew1[256 * H + t];
    }
    if (t >= 128 && t < 640) wea_s[t - 128] = ew1[257 * H + (t - 128)];
    __syncthreads();

    const int half = t >> 9;
    const int t5 = t & 511;
    const int w5 = t5 >> 5;
    const int lane = t5 & 31;
    const int mt5 = w5 >> 2;
    const int ng = w5 & 3;
    const int grp = lane >> 2;
    const int thr = lane & 3;
    const int ee0 = mt5 * 16 + grp, ee1 = ee0 + 8;
    const int hb = half * 4096;
    const int he = half * 64;
    const int NT64 = (N_EDGES + 63) / 64;

    for (int tile = blockIdx.x * 2 + half; tile < NT64; tile += 2 * gridDim.x) {
        const int e0 = tile * 64;
        if (t5 < 64) {
            wsum_s[he + t5] = 0.f;
            int sidx = e0 + t5;
            int r = -1, c = 0, pe = 0;
            if (sidx < N_EDGES) { r = g_srow[sidx]; c = g_scol[sidx]; pe = g_sperm[sidx]; }
            row_s[he + t5] = r; col_s[he + t5] = c;
            float4 a = make_float4(0.f, 0.f, 0.f, 0.f);
            if (r >= 0) a = *(const float4*)&eattr[pe * 4];
            int rr = r < 0 ? 0 : r;
            float rx = g_pos[rr * 3 + 0] - g_pos[c * 3 + 0];
            float ry = g_pos[rr * 3 + 1] - g_pos[c * 3 + 1];
            float rz = g_pos[rr * 3 + 2] - g_pos[c * 3 + 2];
            rel_s[(he + t5) * 3 + 0] = rx; rel_s[(he + t5) * 3 + 1] = ry;
            rel_s[(he + t5) * 3 + 2] = rz;
            d2_s[he + t5] = rx * rx + ry * ry + rz * rz;
            ea_s[(he + t5) * 4 + 0] = a.x; ea_s[(he + t5) * 4 + 1] = a.y;
            ea_s[(he + t5) * 4 + 2] = a.z; ea_s[(he + t5) * 4 + 3] = a.w;
        }
        BARH(half);

        // Phase A
        {
            const int j0 = lane * 4;
            int prevrow = -1;
            float4 p1;
#pragma unroll
            for (int rep = 0; rep < 4; rep++) {
                int e = w5 * 4 + rep;
                int r = row_s[he + e], c = col_s[he + e];
                int rr = r < 0 ? 0 : r;
                if (rr != prevrow) {
                    p1 = *(const float4*)&g_P1[rr * H + j0];
                    prevrow = rr;
                }
                float4 p2 = *(const float4*)&g_P2[c * H + j0];
                float dd = d2_s[he + e];
                float v0 = p1.x + p2.x + dd * wd2_s[j0];
                float v1 = p1.y + p2.y + dd * wd2_s[j0 + 1];
                float v2 = p1.z + p2.z + dd * wd2_s[j0 + 2];
                float v3 = p1.w + p2.w + dd * wd2_s[j0 + 3];
#pragma unroll
                for (int a2 = 0; a2 < 4; a2++) {
                    float eav = ea_s[(he + e) * 4 + a2];
                    v0 += eav * wea_s[a2 * H + j0];
                    v1 += eav * wea_s[a2 * H + j0 + 1];
                    v2 += eav * wea_s[a2 * H + j0 + 2];
                    v3 += eav * wea_s[a2 * H + j0 + 3];
                }
                unsigned lo;
                unsigned hi = split2(silu_f(v0), silu_f(v1), lo);
                int fi = hb + fragAb(e, j0, 8);
                actH[fi] = hi; actL[fi] = lo;
                hi = split2(silu_f(v2), silu_f(v3), lo);
                fi = hb + fragAb(e, j0 + 2, 8);
                actH[fi] = hi; actL[fi] = lo;
            }
        }
        BARH(half);

        // Phase B
        float cB[4][4];
#pragma unroll
        for (int q = 0; q < 4; q++) {
            int jc = (ng * 4 + q) * 8 + 2 * thr;
            cB[q][0] = b2_s[jc]; cB[q][1] = b2_s[jc + 1];
            cB[q][2] = cB[q][0]; cB[q][3] = cB[q][1];
        }
#pragma unroll
        for (int kt = 0; kt < 8; kt++) {
            int aoff = hb + ((((mt5 * 8 + kt) << 5) + lane) << 2);
            uint4 ah = *(const uint4*)&actH[aoff];
            uint4 al = *(const uint4*)&actL[aoff];
#pragma unroll
            for (int q = 0; q < 4; q++) {
                int bi = ((((ng * 4 + q) * 8 + kt) << 5) + lane) << 1;
                uint2 bh = *(const uint2*)&w2F[bi];
                uint2 bl = *(const uint2*)&w2F[8192 + bi];
                mma3(cB[q], ah, al, bh, bl);
            }
        }
        BARH(half);
#pragma unroll
        for (int q = 0; q < 4; q++) {
            int jq = (ng * 4 + q) * 8 + 2 * thr;
            unsigned lo0, lo1;
            unsigned hi0 = split2(silu_f(cB[q][0]), silu_f(cB[q][1]), lo0);
            unsigned hi1 = split2(silu_f(cB[q][2]), silu_f(cB[q][3]), lo1);
            int f0 = hb + fragAb(ee0, jq, 8);
            int f1 = hb + fragAb(ee1, jq, 8);
            actH[f0] = hi0; actL[f0] = lo0;
            actH[f1] = hi1; actL[f1] = lo1;
        }
        BARH(half);

        // Phase C
        {
            float cC[4][4];
#pragma unroll
            for (int q = 0; q < 4; q++) {
                int jc = (ng * 4 + q) * 8 + 2 * thr;
                cC[q][0] = cb1_s[jc]; cC[q][1] = cb1_s[jc + 1];
                cC[q][2] = cC[q][0]; cC[q][3] = cC[q][1];
            }
#pragma unroll
            for (int kt = 0; kt < 8; kt++) {
                int aoff = hb + ((((mt5 * 8 + kt) << 5) + lane) << 2);
                uint4 ah = *(const uint4*)&actH[aoff];
                uint4 al = *(const uint4*)&actL[aoff];
#pragma unroll
                for (int q = 0; q < 4; q++) {
                    int bi = ((((ng * 4 + q) * 8 + kt) << 5) + lane) << 1;
                    uint2 bh = *(const uint2*)&c1F[bi];
                    uint2 bl = *(const uint2*)&c1F[8192 + bi];
                    mma3(cC[q], ah, al, bh, bl);
                }
            }
            float sl = 0.f, sh = 0.f;
#pragma unroll
            for (int q = 0; q < 4; q++) {
                int jq = (ng * 4 + q) * 8 + 2 * thr;
                sl += silu_f(cC[q][0]) * c2_s[jq] + silu_f(cC[q][1]) * c2_s[jq + 1];
                sh += silu_f(cC[q][2]) * c2_s[jq] + silu_f(cC[q][3]) * c2_s[jq + 1];
            }
            sl += __shfl_xor_sync(0xffffffffu, sl, 1);
            sl += __shfl_xor_sync(0xffffffffu, sl, 2);
            sh += __shfl_xor_sync(0xffffffffu, sh, 1);
            sh += __shfl_xor_sync(0xffffffffu, sh, 2);
            if (thr == 0) {
                atomicAdd(&wsum_s[he + ee0], sl);
                atomicAdd(&wsum_s[he + ee1], sh);
            }
        }
        BARH(half);

        // Phase D
        {
            const int jp = t5 & 63;
            const int j0 = jp * 2;
            const int q = t5 >> 6;
            const int ebeg = q * 8;
            float acc0 = 0.f, acc1 = 0.f;
            int cur = row_s[he + ebeg];
#pragma unroll
            for (int i = 0; i < 8; i++) {
                int e = ebeg + i;
                int r = row_s[he + e];
                int fi = hb + fragAb(e, j0, 8);
                unsigned hi = actH[fi], lo = actL[fi];
                float v0 = bfsum(hi, lo);
                float v1 = bfsum(hi >> 16, lo >> 16);
                if (r != cur) {
                    if (cur >= 0) {
                        atomicAdd(&g_agg[cur * H + j0], acc0);
                        atomicAdd(&g_agg[cur * H + j0 + 1], acc1);
                    }
                    acc0 = 0.f; acc1 = 0.f;
                    cur = r;
                }
                acc0 += v0; acc1 += v1;
            }
            if (cur >= 0) {
                atomicAdd(&g_agg[cur * H + j0], acc0);
                atomicAdd(&g_agg[cur * H + j0 + 1], acc1);
            }
        }
        if (t5 < 192) {
            int e = t5 / 3, k = t5 % 3;
            int r = row_s[he + e];
            if (r >= 0)
                atomicAdd(&g_posdelta[r * 3 + k], rel_s[(he + e) * 3 + k] * wsum_s[he + e]);
        }
        BARH(half);
    }
}

// ---------------- fused node update + next-layer proj ----------------
__global__ __launch_bounds__(1024, 1) void k_node(int l, const float* __restrict__ b1n,
                                                  const float* __restrict__ b2n,
                                                  int nextl, const float* __restrict__ b1next) {
    extern __shared__ float sm[];
    unsigned* wF = (unsigned*)sm;   // 32768 (node phases use first 16384)
    unsigned* aH = wF + 32768;      // 4096
    unsigned* aL = aH + 4096;       // 4096
    const int t = threadIdx.x;
    const int n0 = blockIdx.x * 64;
    const int wid = t >> 5, lane = t & 31;
    const int mt = wid >> 3, nt0 = (wid & 7) * 2;
    const int grp = lane >> 2, thr = lane & 3;
    const int ee0 = mt * 16 + grp, ee1 = ee0 + 8;
    const int g0 = n0 + ee0, g1 = n0 + ee1;
    const int j00 = nt0 * 8 + 2 * thr, j10 = (nt0 + 1) * 8 + 2 * thr;

    if (t < 192) {
        int gi = n0 + t / 3;
        if (gi < N_NODES) {
            float d = fmaxf(g_deg[gi], 1.0f);
            g_pos[n0 * 3 + t] += g_posdelta[n0 * 3 + t] / d;
        }
    }

    float c0[4] = {0.f, 0.f, 0.f, 0.f}, c1[4] = {0.f, 0.f, 0.f, 0.f};
    for (int halfk = 0; halfk < 2; halfk++) {
        __syncthreads();
        {
            const uint4* s = (const uint4*)(g_pk_n1 + l * 32768 + halfk * 16384);
            uint4* d = (uint4*)wF;
            for (int i = t; i < 4096; i += 1024) d[i] = s[i];
        }
        const float* src = halfk ? g_agg : g_h;
        for (int i = t; i < 4096; i += 1024) {
            int n = i >> 6, jp = i & 63;
            int j0 = jp * 2;
            int gi = n0 + n;
            float2 v = make_float2(0.f, 0.f);
            if (gi < N_NODES) v = *(const float2*)&src[gi * H + j0];
            unsigned lo;
            unsigned hi = split2(v.x, v.y, lo);
            int fi = fragAb(n, j0, 8);
            aH[fi] = hi;
            aL[fi] = lo;
        }
        __syncthreads();
#pragma unroll
        for (int kt = 0; kt < 8; kt++) {
            int aoff = (((mt * 8 + kt) << 5) + lane) << 2;
            uint4 ah = *(const uint4*)&aH[aoff];
            uint4 al = *(const uint4*)&aL[aoff];
            int bi0 = (((nt0 * 8 + kt) << 5) + lane) << 1;
            int bi1 = ((((nt0 + 1) * 8 + kt) << 5) + lane) << 1;
            uint2 bh0 = *(const uint2*)&wF[bi0];
            uint2 bl0 = *(const uint2*)&wF[8192 + bi0];
            uint2 bh1 = *(const uint2*)&wF[bi1];
            uint2 bl1 = *(const uint2*)&wF[8192 + bi1];
            mma3(c0, ah, al, bh0, bl0);
            mma3(c1, ah, al, bh1, bl1);
        }
    }
    float b00 = __ldg(&b1n[j00]), b01 = __ldg(&b1n[j00 + 1]);
    float b10 = __ldg(&b1n[j10]), b11 = __ldg(&b1n[j10 + 1]);
    float u00 = silu_f(c0[0] + b00), u01 = silu_f(c0[1] + b01);
    float u02 = silu_f(c0[2] + b00), u03 = silu_f(c0[3] + b01);
    float u10 = silu_f(c1[0] + b10), u11 = silu_f(c1[1] + b11);
    float u12 = silu_f(c1[2] + b10), u13 = silu_f(c1[3] + b11);
    __syncthreads();
    {
        unsigned lo;
        unsigned hi;
        int fi;
        hi = split2(u00, u01, lo); fi = fragAb(ee0, j00, 8); aH[fi] = hi; aL[fi] = lo;
        hi = split2(u02, u03, lo); fi = fragAb(ee1, j00, 8); aH[fi] = hi; aL[fi] = lo;
        hi = split2(u10, u11, lo); fi = fragAb(ee0, j10, 8); aH[fi] = hi; aL[fi] = lo;
        hi = split2(u12, u13, lo); fi = fragAb(ee1, j10, 8); aH[fi] = hi; aL[fi] = lo;
    }
    {
        const uint4* s = (const uint4*)(g_pk_n2 + l * 16384);
        uint4* d = (uint4*)wF;
        for (int i = t; i < 4096; i += 1024) d[i] = s[i];
    }
    __syncthreads();

    float d0[4] = {0.f, 0.f, 0.f, 0.f}, d1[4] = {0.f, 0.f, 0.f, 0.f};
#pragma unroll
    for (int kt = 0; kt < 8; kt++) {
        int aoff = (((mt * 8 + kt) << 5) + lane) << 2;
        uint4 ah = *(const uint4*)&aH[aoff];
        uint4 al = *(const uint4*)&aL[aoff];
        int bi0 = (((nt0 * 8 + kt) << 5) + lane) << 1;
        int bi1 = ((((nt0 + 1) * 8 + kt) << 5) + lane) << 1;
        uint2 bh0 = *(const uint2*)&wF[bi0];
        uint2 bl0 = *(const uint2*)&wF[8192 + bi0];
        uint2 bh1 = *(const uint2*)&wF[bi1];
        uint2 bl1 = *(const uint2*)&wF[8192 + bi1];
        mma3(d0, ah, al, bh0, bl0);
        mma3(d1, ah, al, bh1, bl1);
    }
    float e00 = __ldg(&b2n[j00]), e01 = __ldg(&b2n[j00 + 1]);
    float e10 = __ldg(&b2n[j10]), e11 = __ldg(&b2n[j10 + 1]);
    float hn00 = 0.f, hn01 = 0.f, hn02 = 0.f, hn03 = 0.f;
    float hn10 = 0.f, hn11 = 0.f, hn12 = 0.f, hn13 = 0.f;
    if (g0 < N_NODES) {
        float2 h0 = *(float2*)&g_h[g0 * H + j00];
        hn00 = h0.x + d0[0] + e00; hn01 = h0.y + d0[1] + e01;
        *(float2*)&g_h[g0 * H + j00] = make_float2(hn00, hn01);
        float2 h1 = *(float2*)&g_h[g0 * H + j10];
        hn02 = h1.x + d1[0] + e10; hn03 = h1.y + d1[1] + e11;
        *(float2*)&g_h[g0 * H + j10] = make_float2(hn02, hn03);
    }
    if (g1 < N_NODES) {
        float2 h0 = *(float2*)&g_h[g1 * H + j00];
        hn10 = h0.x + d0[2] + e00; hn11 = h0.y + d0[3] + e01;
        *(float2*)&g_h[g1 * H + j00] = make_float2(hn10, hn11);
        float2 h1 = *(float2*)&g_h[g1 * H + j10];
        hn12 = h1.x + d1[2] + e10; hn13 = h1.y + d1[3] + e11;
        *(float2*)&g_h[g1 * H + j10] = make_float2(hn12, hn13);
    }

    if (nextl >= NLAYERS) return;

    // ---- fused proj for layer nextl ----
    __syncthreads();
    {
        unsigned lo;
        unsigned hi;
        int fi;
        hi = split2(hn00, hn01, lo); fi = fragAb(ee0, j00, 8); aH[fi] = hi; aL[fi] = lo;
        hi = split2(hn02, hn03, lo); fi = fragAb(ee0, j10, 8); aH[fi] = hi; aL[fi] = lo;
        hi = split2(hn10, hn11, lo); fi = fragAb(ee1, j00, 8); aH[fi] = hi; aL[fi] = lo;
        hi = split2(hn12, hn13, lo); fi = fragAb(ee1, j10, 8); aH[fi] = hi; aL[fi] = lo;
    }
    {
        const uint4* s = (const uint4*)(g_pk_proj + nextl * 32768);
        uint4* d = (uint4*)wF;
        for (int i = t; i < 8192; i += 1024) d[i] = s[i];
    }
    {
        const float4 z4 = make_float4(0.f, 0.f, 0.f, 0.f);
        for (int i = t; i < 2048; i += 1024) {
            int gi = n0 + (i >> 5);
            if (gi < N_NODES) *(float4*)&g_agg[gi * H + (i & 31) * 4] = z4;
        }
    }
    if (t < 192) {
        int gi = n0 + t / 3;
        if (gi < N_NODES) g_posdelta[gi * 3 + t % 3] = 0.f;
    }
    __syncthreads();

    const int ngp = wid & 7;
    float c[4][4];
#pragma unroll
    for (int q = 0; q < 4; q++)
#pragma unroll
        for (int r = 0; r < 4; r++) c[q][r] = 0.f;
#pragma unroll
    for (int kt = 0; kt < 8; kt++) {
        int aoff = (((mt * 8 + kt) << 5) + lane) << 2;
        uint4 ah = *(const uint4*)&aH[aoff];
        uint4 al = *(const uint4*)&aL[aoff];
#pragma unroll
        for (int q = 0; q < 4; q++) {
            int nt = ngp * 4 + q;
            int bi = (((nt * 8 + kt) << 5) + lane) << 1;
            uint2 bh = *(const uint2*)&wF[bi];
            uint2 bl = *(const uint2*)&wF[16384 + bi];
            mma3(c[q], ah, al, bh, bl);
        }
    }
#pragma unroll
    for (int q = 0; q < 4; q++) {
        int nt = ngp * 4 + q;
        int jj0 = nt * 8 + 2 * thr;
        int half = jj0 >> 7;
        int j = jj0 & 127;
        float* outp = half ? g_P2 : g_P1;
        float bb0 = half ? 0.f : __ldg(&b1next[j]);
        float bb1 = half ? 0.f : __ldg(&b1next[j + 1]);
        if (g0 < N_NODES)
            *(float2*)&outp[g0 * H + j] = make_float2(c[q][0] + bb0, c[q][1] + bb1);
        if (g1 < N_NODES)
            *(float2*)&outp[g1 * H + j] = make_float2(c[q][2] + bb0, c[q][3] + bb1);
    }
}

// ---------------- pooling + readout head fused ----------------
__global__ __launch_bounds__(512) void k_poolhead(
    const float* __restrict__ h1_w, const float* __restrict__ h1_b,
    const float* __restrict__ h2_w, const float* __restrict__ h2_b,
    const float* __restrict__ h3_w, const float* __restrict__ h3_b,
    float* __restrict__ out) {
    __shared__ float red[512], gf[256], z1[128], z2[64];
    const int g = blockIdx.x, t = threadIdx.x;
    const int j = t & 127, w = t >> 7;
    float s = 0.f;
    for (int n = w; n < NPG; n += 4) s += g_h[(g * NPG + n) * H + j];
    red[t] = s;
    __syncthreads();
    if (w == 0) {
        float tot = red[j] + red[128 + j] + red[256 + j] + red[384 + j];
        gf[j] = tot;
        gf[128 + j] = tot * (1.f / (float)NPG);
    }
    __syncthreads();
    if (t < 128) {
        float a = h1_b[t];
        for (int k = 0; k < 256; k++) a += gf[k] * h1_w[k * 128 + t];
        z1[t] = fmaxf(a, 0.f);
    }
    __syncthreads();
    if (t < 64) {
        float a2 = h2_b[t];
        for (int k = 0; k < 128; k++) a2 += z1[k] * h2_w[k * 64 + t];
        z2[t] = fmaxf(a2, 0.f);
    }
    __syncthreads();
    if (t == 0) {
        float a3 = h3_b[0];
        for (int k = 0; k < 64; k++) a3 += z2[k] * h3_w[k];
        out[g] = a3;
    }
}

// ---------------- launch ----------------
extern "C" void kernel_launch(void* const* d_in, const int* in_sizes, int n_in,
                              void* d_out, int out_size) {
    const float* x     = (const float*)d_in[0];
    const float* pos   = (const float*)d_in[1];
    const int*   ei    = (const int*)d_in[2];
    const float* eattr = (const float*)d_in[3];
    const float* Wp    = (const float*)d_in[6];
    const float* bp    = (const float*)d_in[7];
    const float* Wl    = (const float*)d_in[8];
    const float* bl    = (const float*)d_in[9];
    const float* gamma = (const float*)d_in[10];
    const float* beta  = (const float*)d_in[11];
    const float* e_w1  = (const float*)d_in[12];
    const float* e_b1  = (const float*)d_in[13];
    const float* e_w2  = (const float*)d_in[14];
    const float* e_b2  = (const float*)d_in[15];
    const float* c_w1  = (const float*)d_in[16];
    const float* c_b1  = (const float*)d_in[17];
    const float* c_w2  = (const float*)d_in[18];
    const float* n_w1  = (const float*)d_in[19];
    const float* n_b1  = (const float*)d_in[20];
    const float* n_w2  = (const float*)d_in[21];
    const float* n_b2  = (const float*)d_in[22];
    const float* h1_w  = (const float*)d_in[23];
    const float* h1_b  = (const float*)d_in[24];
    const float* h2_w  = (const float*)d_in[25];
    const float* h2_b  = (const float*)d_in[26];
    const float* h3_w  = (const float*)d_in[27];
    const float* h3_b  = (const float*)d_in[28];
    float* out = (float*)d_out;

    const int PROJ_SMEM = (32768 + 4096 + 4096) * 4;
    const int EDGE_SMEM = (16384 * 2 + 8192 * 2 + 128 * 4 + 512
                           + 128 + 384 + 512 + 128 + 128 + 128) * 4;
    const int NODE_SMEM = (32768 + 4096 + 4096) * 4;
    cudaFuncSetAttribute(k_proj0, cudaFuncAttributeMaxDynamicSharedMemorySize, PROJ_SMEM);
    cudaFuncSetAttribute(k_edge, cudaFuncAttributeMaxDynamicSharedMemorySize, EDGE_SMEM);
    cudaFuncSetAttribute(k_node, cudaFuncAttributeMaxDynamicSharedMemorySize, NODE_SMEM);

    k_embed<<<N_NODES, 128>>>(x, pos, Wp, bp, Wl, bl);
    k_prep<<<256 + DEG_BLOCKS + PACK_BLOCKS, 512>>>(ei, e_w1, e_w2, c_w1, n_w1, n_w2);
    // K3: block0 = scan, blocks 1..PERM_BLOCKS = perm (spin on flag), rest = proj0+BN
    k_proj0<<<1 + PERM_BLOCKS + NB64, 1024, PROJ_SMEM>>>(ei, e_b1, gamma, beta);

    for (int l = 0; l < NLAYERS; l++) {
        k_edge<<<148, 1024, EDGE_SMEM>>>(eattr, l, e_b2 + l * H, c_b1 + l * H,
                                         c_w2 + l * H, e_w1 + l * 261 * H);
        int nextl = l + 1;
        const float* b1next = (nextl < NLAYERS) ? (e_b1 + nextl * H) : e_b1;
        k_node<<<NB64, 1024, NODE_SMEM>>>(l, n_b1 + l * H, n_b2 + l * H, nextl, b1next);
    }

    k_poolhead<<<G_GRAPHS, 512>>>(h1_w, h1_b, h2_w, h2_b, h3_w, h3_b, out);
}

// round 17
// speedup vs baseline: 1.0153x; 1.0153x over previous
#include <cuda_runtime.h>
#include <cuda_bf16.h>

#define N_NODES 50000
#define N_EDGES 500000
#define H 128
#define G_GRAPHS 100
#define NPG 500
#define NPROT 400
#define PN 35
#define LN 11
#define NLAYERS 4
#define EPS 1e-5f

// ---------------- scratch ----------------
__device__ float g_h[N_NODES * H];
__device__ float g_P1[N_NODES * H];
__device__ float g_P2[N_NODES * H];
__device__ float g_agg[N_NODES * H];
__device__ float g_pos[N_NODES * 3];
__device__ float g_posdelta[N_NODES * 3];
__device__ float g_deg[N_NODES];
__device__ float g_bnstats[2 * H];
__device__ int g_rowcur[N_NODES];
__device__ int g_srow[N_EDGES];
__device__ int g_scol[N_EDGES];
__device__ int g_sperm[N_EDGES];
__device__ int g_flag;
// pre-packed bf16 hi/lo weight fragments
__device__ unsigned g_pk_proj[NLAYERS * 32768];  // hi 16384 | lo 16384
__device__ unsigned g_pk_w2[NLAYERS * 16384];    // INTERLEAVED uint4 {bh0,bh1,bl0,bl1}
__device__ unsigned g_pk_c1[NLAYERS * 16384];    // INTERLEAVED
__device__ unsigned g_pk_n1[NLAYERS * 32768];    // [half0: hi|lo][half1: hi|lo]
__device__ unsigned g_pk_n2[NLAYERS * 16384];    // hi 8192 | lo 8192

__device__ __forceinline__ float silu_f(float x) {
    return x / (1.f + __expf(-x));
}

// ---- bf16 m16n8k16 mma ----
__device__ __forceinline__ void mma_bf16(float* c, const uint4& a, const uint2& b) {
    asm volatile(
        "mma.sync.aligned.m16n8k16.row.col.f32.bf16.bf16.f32 "
        "{%0,%1,%2,%3}, {%4,%5,%6,%7}, {%8,%9}, {%0,%1,%2,%3};"
        : "+f"(c[0]), "+f"(c[1]), "+f"(c[2]), "+f"(c[3])
        : "r"(a.x), "r"(a.y), "r"(a.z), "r"(a.w), "r"(b.x), "r"(b.y));
}
__device__ __forceinline__ unsigned split2(float v0, float v1, unsigned& lo) {
    __nv_bfloat16 h0 = __float2bfloat16(v0);
    __nv_bfloat16 h1 = __float2bfloat16(v1);
    __nv_bfloat16 l0 = __float2bfloat16(v0 - __bfloat162float(h0));
    __nv_bfloat16 l1 = __float2bfloat16(v1 - __bfloat162float(h1));
    lo = (unsigned)__bfloat16_as_ushort(l0) | ((unsigned)__bfloat16_as_ushort(l1) << 16);
    return (unsigned)__bfloat16_as_ushort(h0) | ((unsigned)__bfloat16_as_ushort(h1) << 16);
}
__device__ __forceinline__ void mma3(float* c, const uint4& ah, const uint4& al,
                                     const uint2& bh, const uint2& bl) {
    mma_bf16(c, ah, bh);
    mma_bf16(c, ah, bl);
    mma_bf16(c, al, bh);
}
// 3-MMA from interleaved uint4 {bh0,bh1,bl0,bl1}
__device__ __forceinline__ void mma3i(float* c, const uint4& ah, const uint4& al,
                                      const uint4& bb) {
    uint2 bh = make_uint2(bb.x, bb.y);
    uint2 bl = make_uint2(bb.z, bb.w);
    mma_bf16(c, ah, bh);
    mma_bf16(c, ah, bl);
    mma_bf16(c, al, bh);
}
__device__ __forceinline__ int fragAb(int e, int j0, int KT) {
    int jin = j0 & 15;
    int tid = (jin & 7) >> 1;
    int reg = ((jin >> 3) << 1) | ((e >> 3) & 1);
    int lane = ((e & 7) << 2) | tid;
    return (((e >> 4) * KT + (j0 >> 4)) << 7) + (lane << 2) + reg;
}
__device__ __forceinline__ float bfsum(unsigned hi, unsigned lo) {
    return __bfloat162float(__ushort_as_bfloat16((unsigned short)(hi & 0xffffu)))
         + __bfloat162float(__ushort_as_bfloat16((unsigned short)(lo & 0xffffu)));
}
#define BARH(hid) asm volatile("bar.sync %0, %1;" :: "r"((hid) + 1), "r"(512) : "memory")

// ---------------- K1: embed ----------------
__global__ void k_embed(const float* __restrict__ x, const float* __restrict__ pos_in,
                        const float* __restrict__ Wp, const float* __restrict__ bp,
                        const float* __restrict__ Wl, const float* __restrict__ bl) {
    __shared__ float xs[PN];
    const int i = blockIdx.x;
    const int t = threadIdx.x;
    if (t < PN) xs[t] = x[i * PN + t];
    if (t == 0) g_deg[i] = 0.f;
    if (t < 3) g_pos[i * 3 + t] = pos_in[i * 3 + t];
    if (i == 0 && t < H) { g_bnstats[t] = 0.f; g_bnstats[H + t] = 0.f; }
    if (i == 0 && t == 0) g_flag = 0;
    __syncthreads();
    const bool isp = (i % NPG) < NPROT;
    const float* W = isp ? Wp : Wl;
    const float* b = isp ? bp : bl;
    const int nk = isp ? PN : LN;
    float acc = b[t];
    for (int k = 0; k < nk; k++) acc += xs[k] * W[k * H + t];
    g_h[i * H + t] = acc;
}

// ---------------- K2: prep = bnstats + deg + weight pack ----------------
#define DEG_BLOCKS ((N_EDGES + 511) / 512)
#define PACK_PER_LAYER (16384 + 8192 + 8192 + 16384 + 8192)  // 57344
#define PACK_ITEMS (NLAYERS * PACK_PER_LAYER)
#define PACK_BLOCKS ((PACK_ITEMS + 511) / 512)
__global__ __launch_bounds__(512) void k_prep(const int* __restrict__ ei,
                                              const float* __restrict__ ew1,
                                              const float* __restrict__ ew2,
                                              const float* __restrict__ cw1,
                                              const float* __restrict__ nw1,
                                              const float* __restrict__ nw2) {
    const int t = threadIdx.x;
    if (blockIdx.x < 256) {
        const int j = t & 127;
        const int g2 = t >> 7;
        float s = 0.f, s2 = 0.f;
        for (int i = blockIdx.x * 4 + g2; i < N_NODES; i += 1024) {
            float v = g_h[i * H + j];
            s += v; s2 += v * v;
        }
        atomicAdd(&g_bnstats[j], s);
        atomicAdd(&g_bnstats[H + j], s2);
        return;
    }
    if (blockIdx.x < 256 + DEG_BLOCKS) {
        const int e = (blockIdx.x - 256) * 512 + t;
        if (e < N_EDGES) atomicAdd(&g_deg[ei[e]], 1.0f);
        return;
    }
    int idx = (blockIdx.x - 256 - DEG_BLOCKS) * 512 + t;
    if (idx >= PACK_ITEMS) return;
    int l = idx / PACK_PER_LAYER;
    int o = idx - l * PACK_PER_LAYER;
    float w0, w1;
    unsigned* hip;
    unsigned* lop;
    if (o < 16384) {            // proj (hi|lo split layout)
        int i = o;
        int rb = i & 1, lane = (i >> 1) & 31, kt = (i >> 6) & 7, nt = i >> 9;
        int tid = lane & 3, g = lane >> 2;
        int k0 = kt * 16 + tid * 2 + rb * 8;
        int jj = nt * 8 + g;
        const float* W = ew1 + l * 261 * H;
        int srcrow = (jj < 128) ? k0 : (128 + k0);
        int col = jj & 127;
        w0 = W[srcrow * H + col];
        w1 = W[(srcrow + 1) * H + col];
        hip = g_pk_proj + l * 32768 + i;
        lop = hip + 16384;
    } else if (o < 24576) {     // w2: INTERLEAVED uint4 layout
        int i = o - 16384;
        int rb = i & 1, lane = (i >> 1) & 31, kt = (i >> 6) & 7, nt = i >> 9;
        int tid = lane & 3, g = lane >> 2;
        int k0 = kt * 16 + tid * 2 + rb * 8;
        int n = nt * 8 + g;
        const float* W = ew2 + l * H * H;
        w0 = W[k0 * H + n];
        w1 = W[(k0 + 1) * H + n];
        hip = g_pk_w2 + l * 16384 + (((nt * 8 + kt) * 32 + lane) * 4 + rb);
        lop = hip + 2;
    } else if (o < 32768) {     // c1: INTERLEAVED
        int i = o - 24576;
        int rb = i & 1, lane = (i >> 1) & 31, kt = (i >> 6) & 7, nt = i >> 9;
        int tid = lane & 3, g = lane >> 2;
        int k0 = kt * 16 + tid * 2 + rb * 8;
        int n = nt * 8 + g;
        const float* W = cw1 + l * H * H;
        w0 = W[k0 * H + n];
        w1 = W[(k0 + 1) * H + n];
        hip = g_pk_c1 + l * 16384 + (((nt * 8 + kt) * 32 + lane) * 4 + rb);
        lop = hip + 2;
    } else if (o < 49152) {     // n1 (per-half hi|lo split)
        int i2 = o - 32768;
        int hk = i2 >> 13;
        int i = i2 & 8191;
        int rb = i & 1, lane = (i >> 1) & 31, kt = (i >> 6) & 7, nt = i >> 9;
        int tid = lane & 3, g = lane >> 2;
        int k0 = hk * 128 + kt * 16 + tid * 2 + rb * 8;
        int n = nt * 8 + g;
        const float* W = nw1 + l * 2 * H * H;
        w0 = W[k0 * H + n];
        w1 = W[(k0 + 1) * H + n];
        hip = g_pk_n1 + l * 32768 + hk * 16384 + i;
        lop = hip + 8192;
    } else {                    // n2 (hi|lo split)
        int i = o - 49152;
        int rb = i & 1, lane = (i >> 1) & 31, kt = (i >> 6) & 7, nt = i >> 9;
        int tid = lane & 3, g = lane >> 2;
        int k0 = kt * 16 + tid * 2 + rb * 8;
        int n = nt * 8 + g;
        const float* W = nw2 + l * H * H;
        w0 = W[k0 * H + n];
        w1 = W[(k0 + 1) * H + n];
        hip = g_pk_n2 + l * 16384 + i;
        lop = hip + 8192;
    }
    unsigned lo;
    unsigned hi = split2(w0, w1, lo);
    *hip = hi;
    *lop = lo;
}

// ---------------- K3: scan(block 0) + perm(spin) + proj0+BN ----------------
#define NB64 ((N_NODES + 63) / 64)
#define PERM_BLOCKS ((N_EDGES + 1023) / 1024)   // 489
__global__ __launch_bounds__(1024, 1) void k_proj0(const int* __restrict__ ei,
                                                   const float* __restrict__ b1,
                                                   const float* __restrict__ gamma,
                                                   const float* __restrict__ beta) {
    extern __shared__ float sm[];
    const int t = threadIdx.x;
    if (blockIdx.x == 0) {
        int* sums = (int*)sm;
        const int chunk = 49;
        int base = t * chunk;
        int lim = min(base + chunk, N_NODES);
        int s = 0;
        for (int i = base; i < lim; i++) s += (int)g_deg[i];
        sums[t] = s;
        __syncthreads();
        for (int off = 1; off < 1024; off <<= 1) {
            int v = (t >= off) ? sums[t - off] : 0;
            __syncthreads();
            sums[t] += v;
            __syncthreads();
        }
        int run = (t == 0) ? 0 : sums[t - 1];
        for (int i = base; i < lim; i++) {
            g_rowcur[i] = run;
            run += (int)g_deg[i];
        }
        __threadfence();
        __syncthreads();
        if (t == 0) atomicExch(&g_flag, 1);
        return;
    }
    if (blockIdx.x <= PERM_BLOCKS) {
        if (t == 0) {
            while (atomicAdd(&g_flag, 0) == 0) __nanosleep(64);
        }
        __syncthreads();
        int e = (blockIdx.x - 1) * 1024 + t;
        if (e < N_EDGES) {
            int r = ei[e];
            int p = atomicAdd(&g_rowcur[r], 1);
            g_srow[p] = r;
            g_scol[p] = ei[N_EDGES + e];
            g_sperm[p] = e;
        }
        return;
    }

    unsigned* wF = (unsigned*)sm;       // 32768
    unsigned* aH = wF + 32768;          // 4096
    unsigned* aL = aH + 4096;           // 4096
    const int n0 = (blockIdx.x - 1 - PERM_BLOCKS) * 64;

    {
        const uint4* s = (const uint4*)(g_pk_proj);
        uint4* d = (uint4*)wF;
        for (int i = t; i < 8192; i += 1024) d[i] = s[i];
    }
    const float inv_n = 1.f / (float)N_NODES;
    for (int i = t; i < 4096; i += 1024) {
        int n = i >> 6, jp = i & 63;
        int j0 = jp * 2;
        int gi = n0 + n;
        float2 v = make_float2(0.f, 0.f);
        if (gi < N_NODES) {
            v = *(const float2*)&g_h[gi * H + j0];
            float mu0 = g_bnstats[j0] * inv_n;
            float mu1 = g_bnstats[j0 + 1] * inv_n;
            float var0 = g_bnstats[H + j0] * inv_n - mu0 * mu0;
            float var1 = g_bnstats[H + j0 + 1] * inv_n - mu1 * mu1;
            v.x = (v.x - mu0) * rsqrtf(var0 + EPS) * gamma[j0] + beta[j0];
            v.y = (v.y - mu1) * rsqrtf(var1 + EPS) * gamma[j0 + 1] + beta[j0 + 1];
            *(float2*)&g_h[gi * H + j0] = v;
        }
        unsigned lo;
        unsigned hi = split2(v.x, v.y, lo);
        int fi = fragAb(n, j0, 8);
        aH[fi] = hi;
        aL[fi] = lo;
    }
    {
        const float4 z4 = make_float4(0.f, 0.f, 0.f, 0.f);
        for (int i = t; i < 2048; i += 1024) {
            int gi = n0 + (i >> 5);
            if (gi < N_NODES) *(float4*)&g_agg[gi * H + (i & 31) * 4] = z4;
        }
    }
    if (t < 192) {
        int gi = n0 + t / 3;
        if (gi < N_NODES) g_posdelta[gi * 3 + t % 3] = 0.f;
    }
    __syncthreads();

    const int wid = t >> 5, lane = t & 31;
    const int mt = wid >> 3;
    const int ng = wid & 7;
    const int grp = lane >> 2, thr = lane & 3;
    float c[4][4];
#pragma unroll
    for (int q = 0; q < 4; q++)
#pragma unroll
        for (int r = 0; r < 4; r++) c[q][r] = 0.f;

#pragma unroll
    for (int kt = 0; kt < 8; kt++) {
        int aoff = (((mt * 8 + kt) << 5) + lane) << 2;
        uint4 ah = *(const uint4*)&aH[aoff];
        uint4 al = *(const uint4*)&aL[aoff];
#pragma unroll
        for (int q = 0; q < 4; q++) {
            int nt = ng * 4 + q;
            int bi = (((nt * 8 + kt) << 5) + lane) << 1;
            uint2 bh = *(const uint2*)&wF[bi];
            uint2 bl = *(const uint2*)&wF[16384 + bi];
            mma3(c[q], ah, al, bh, bl);
        }
    }

    const int ee0 = mt * 16 + grp, ee1 = ee0 + 8;
    const int g0 = n0 + ee0, g1 = n0 + ee1;
#pragma unroll
    for (int q = 0; q < 4; q++) {
        int nt = ng * 4 + q;
        int jj0 = nt * 8 + 2 * thr;
        int half = jj0 >> 7;
        int j = jj0 & 127;
        float* outp = half ? g_P2 : g_P1;
        float bb0 = half ? 0.f : __ldg(&b1[j]);
        float bb1 = half ? 0.f : __ldg(&b1[j + 1]);
        if (g0 < N_NODES)
            *(float2*)&outp[g0 * H + j] = make_float2(c[q][0] + bb0, c[q][1] + bb1);
        if (g1 < N_NODES)
            *(float2*)&outp[g1 * H + j] = make_float2(c[q][2] + bb0, c[q][3] + bb1);
    }
}

// ---------------- fused edge kernel: two pipelines, interleaved B loads ----------------
__global__ __launch_bounds__(1024, 1) void k_edge(
    const float* __restrict__ eattr, int l,
    const float* __restrict__ b2, const float* __restrict__ cb1,
    const float* __restrict__ cw2, const float* __restrict__ ew1) {
    extern __shared__ float sm[];
    unsigned* w2F = (unsigned*)sm;       // 16384 interleaved
    unsigned* c1F = w2F + 16384;         // 16384 interleaved
    unsigned* actH = c1F + 16384;        // 8192
    unsigned* actL = actH + 8192;        // 8192
    float* b2_s  = (float*)(actL + 8192);  // 128
    float* cb1_s = b2_s + 128;           // 128
    float* c2_s  = cb1_s + 128;          // 128
    float* wd2_s = c2_s + 128;           // 128
    float* wea_s = wd2_s + 128;          // 512
    float* d2_s  = wea_s + 512;          // 128
    float* rel_s = d2_s + 128;           // 384
    float* ea_s  = rel_s + 384;          // 512
    float* wsum_s = ea_s + 512;          // 128
    int* row_s = (int*)(wsum_s + 128);   // 128
    int* col_s = row_s + 128;            // 128

    const int t = threadIdx.x;
    {
        const uint4* s2 = (const uint4*)(g_pk_w2 + l * 16384);
        const uint4* s1 = (const uint4*)(g_pk_c1 + l * 16384);
        uint4* d2 = (uint4*)w2F;
        uint4* d1 = (uint4*)c1F;
        for (int i = t; i < 4096; i += 1024) { d2[i] = s2[i]; d1[i] = s1[i]; }
    }
    if (t < 128) {
        b2_s[t] = b2[t]; cb1_s[t] = cb1[t]; c2_s[t] = cw2[t];
        wd2_s[t] = ew1[256 * H + t];
    }
    if (t >= 128 && t < 640) wea_s[t - 128] = ew1[257 * H + (t - 128)];
    __syncthreads();

    const int half = t >> 9;
    const int t5 = t & 511;
    const int w5 = t5 >> 5;
    const int lane = t5 & 31;
    const int mt5 = w5 >> 2;
    const int ng = w5 & 3;
    const int grp = lane >> 2;
    const int thr = lane & 3;
    const int ee0 = mt5 * 16 + grp, ee1 = ee0 + 8;
    const int hb = half * 4096;
    const int he = half * 64;
    const int NT64 = (N_EDGES + 63) / 64;

    for (int tile = blockIdx.x * 2 + half; tile < NT64; tile += 2 * gridDim.x) {
        const int e0 = tile * 64;
        if (t5 < 64) {
            wsum_s[he + t5] = 0.f;
            int sidx = e0 + t5;
            int r = -1, c = 0, pe = 0;
            if (sidx < N_EDGES) { r = g_srow[sidx]; c = g_scol[sidx]; pe = g_sperm[sidx]; }
            row_s[he + t5] = r; col_s[he + t5] = c;
            float4 a = make_float4(0.f, 0.f, 0.f, 0.f);
            if (r >= 0) a = *(const float4*)&eattr[pe * 4];
            int rr = r < 0 ? 0 : r;
            float rx = g_pos[rr * 3 + 0] - g_pos[c * 3 + 0];
            float ry = g_pos[rr * 3 + 1] - g_pos[c * 3 + 1];
            float rz = g_pos[rr * 3 + 2] - g_pos[c * 3 + 2];
            rel_s[(he + t5) * 3 + 0] = rx; rel_s[(he + t5) * 3 + 1] = ry;
            rel_s[(he + t5) * 3 + 2] = rz;
            d2_s[he + t5] = rx * rx + ry * ry + rz * rz;
            ea_s[(he + t5) * 4 + 0] = a.x; ea_s[(he + t5) * 4 + 1] = a.y;
            ea_s[(he + t5) * 4 + 2] = a.z; ea_s[(he + t5) * 4 + 3] = a.w;
        }
        BARH(half);

        // Phase A
        {
            const int j0 = lane * 4;
            int prevrow = -1;
            float4 p1;
#pragma unroll
            for (int rep = 0; rep < 4; rep++) {
                int e = w5 * 4 + rep;
                int r = row_s[he + e], c = col_s[he + e];
                int rr = r < 0 ? 0 : r;
                if (rr != prevrow) {
                    p1 = *(const float4*)&g_P1[rr * H + j0];
                    prevrow = rr;
                }
                float4 p2 = *(const float4*)&g_P2[c * H + j0];
                float dd = d2_s[he + e];
                float v0 = p1.x + p2.x + dd * wd2_s[j0];
                float v1 = p1.y + p2.y + dd * wd2_s[j0 + 1];
                float v2 = p1.z + p2.z + dd * wd2_s[j0 + 2];
                float v3 = p1.w + p2.w + dd * wd2_s[j0 + 3];
#pragma unroll
                for (int a2 = 0; a2 < 4; a2++) {
                    float eav = ea_s[(he + e) * 4 + a2];
                    v0 += eav * wea_s[a2 * H + j0];
                    v1 += eav * wea_s[a2 * H + j0 + 1];
                    v2 += eav * wea_s[a2 * H + j0 + 2];
                    v3 += eav * wea_s[a2 * H + j0 + 3];
                }
                unsigned lo;
                unsigned hi = split2(silu_f(v0), silu_f(v1), lo);
                int fi = hb + fragAb(e, j0, 8);
                actH[fi] = hi; actL[fi] = lo;
                hi = split2(silu_f(v2), silu_f(v3), lo);
                fi = hb + fragAb(e, j0 + 2, 8);
                actH[fi] = hi; actL[fi] = lo;
            }
        }
        BARH(half);

        // Phase B
        float cB[4][4];
#pragma unroll
        for (int q = 0; q < 4; q++) {
            int jc = (ng * 4 + q) * 8 + 2 * thr;
            cB[q][0] = b2_s[jc]; cB[q][1] = b2_s[jc + 1];
            cB[q][2] = cB[q][0]; cB[q][3] = cB[q][1];
        }
#pragma unroll
        for (int kt = 0; kt < 8; kt++) {
            int aoff = hb + ((((mt5 * 8 + kt) << 5) + lane) << 2);
            uint4 ah = *(const uint4*)&actH[aoff];
            uint4 al = *(const uint4*)&actL[aoff];
#pragma unroll
            for (int q = 0; q < 4; q++) {
                int bi = ((((ng * 4 + q) * 8 + kt) << 5) + lane) << 2;
                uint4 bb = *(const uint4*)&w2F[bi];
                mma3i(cB[q], ah, al, bb);
            }
        }
        BARH(half);
#pragma unroll
        for (int q = 0; q < 4; q++) {
            int jq = (ng * 4 + q) * 8 + 2 * thr;
            unsigned lo0, lo1;
            unsigned hi0 = split2(silu_f(cB[q][0]), silu_f(cB[q][1]), lo0);
            unsigned hi1 = split2(silu_f(cB[q][2]), silu_f(cB[q][3]), lo1);
            int f0 = hb + fragAb(ee0, jq, 8);
            int f1 = hb + fragAb(ee1, jq, 8);
            actH[f0] = hi0; actL[f0] = lo0;
            actH[f1] = hi1; actL[f1] = lo1;
        }
        BARH(half);

        // Phase C
        {
            float cC[4][4];
#pragma unroll
            for (int q = 0; q < 4; q++) {
                int jc = (ng * 4 + q) * 8 + 2 * thr;
                cC[q][0] = cb1_s[jc]; cC[q][1] = cb1_s[jc + 1];
                cC[q][2] = cC[q][0]; cC[q][3] = cC[q][1];
            }
#pragma unroll
            for (int kt = 0; kt < 8; kt++) {
                int aoff = hb + ((((mt5 * 8 + kt) << 5) + lane) << 2);
                uint4 ah = *(const uint4*)&actH[aoff];
                uint4 al = *(const uint4*)&actL[aoff];
#pragma unroll
                for (int q = 0; q < 4; q++) {
                    int bi = ((((ng * 4 + q) * 8 + kt) << 5) + lane) << 2;
                    uint4 bb = *(const uint4*)&c1F[bi];
                    mma3i(cC[q], ah, al, bb);
                }
            }
            float sl = 0.f, sh = 0.f;
#pragma unroll
            for (int q = 0; q < 4; q++) {
                int jq = (ng * 4 + q) * 8 + 2 * thr;
                sl += silu_f(cC[q][0]) * c2_s[jq] + silu_f(cC[q][1]) * c2_s[jq + 1];
                sh += silu_f(cC[q][2]) * c2_s[jq] + silu_f(cC[q][3]) * c2_s[jq + 1];
            }
            sl += __shfl_xor_sync(0xffffffffu, sl, 1);
            sl += __shfl_xor_sync(0xffffffffu, sl, 2);
            sh += __shfl_xor_sync(0xffffffffu, sh, 1);
            sh += __shfl_xor_sync(0xffffffffu, sh, 2);
            if (thr == 0) {
                atomicAdd(&wsum_s[he + ee0], sl);
                atomicAdd(&wsum_s[he + ee1], sh);
            }
        }
        BARH(half);

        // Phase D
        {
            const int jp = t5 & 63;
            const int j0 = jp * 2;
            const int q = t5 >> 6;
            const int ebeg = q * 8;
            float acc0 = 0.f, acc1 = 0.f;
            int cur = row_s[he + ebeg];
#pragma unroll
            for (int i = 0; i < 8; i++) {
                int e = ebeg + i;
                int r = row_s[he + e];
                int fi = hb + fragAb(e, j0, 8);
                unsigned hi = actH[fi], lo = actL[fi];
                float v0 = bfsum(hi, lo);
                float v1 = bfsum(hi >> 16, lo >> 16);
                if (r != cur) {
                    if (cur >= 0) {
                        atomicAdd(&g_agg[cur * H + j0], acc0);
                        atomicAdd(&g_agg[cur * H + j0 + 1], acc1);
                    }
                    acc0 = 0.f; acc1 = 0.f;
                    cur = r;
                }
                acc0 += v0; acc1 += v1;
            }
            if (cur >= 0) {
                atomicAdd(&g_agg[cur * H + j0], acc0);
                atomicAdd(&g_agg[cur * H + j0 + 1], acc1);
            }
        }
        if (t5 < 192) {
            int e = t5 / 3, k = t5 % 3;
            int r = row_s[he + e];
            if (r >= 0)
                atomicAdd(&g_posdelta[r * 3 + k], rel_s[(he + e) * 3 + k] * wsum_s[he + e]);
        }
        BARH(half);
    }
}

// ---------------- fused node update (single-pass K=256) + next-layer proj ----------------
__global__ __launch_bounds__(1024, 1) void k_node(int l, const float* __restrict__ b1n,
                                                  const float* __restrict__ b2n,
                                                  int nextl, const float* __restrict__ b1next) {
    extern __shared__ float sm[];
    unsigned* wF = (unsigned*)sm;   // 32768
    unsigned* aH = wF + 32768;      // 8192 (KT=16 fragments for K=256)
    unsigned* aL = aH + 8192;       // 8192
    const int t = threadIdx.x;
    const int n0 = blockIdx.x * 64;
    const int wid = t >> 5, lane = t & 31;
    const int mt = wid >> 3, nt0 = (wid & 7) * 2;
    const int grp = lane >> 2, thr = lane & 3;
    const int ee0 = mt * 16 + grp, ee1 = ee0 + 8;
    const int g0 = n0 + ee0, g1 = n0 + ee1;
    const int j00 = nt0 * 8 + 2 * thr, j10 = (nt0 + 1) * 8 + 2 * thr;

    if (t < 192) {
        int gi = n0 + t / 3;
        if (gi < N_NODES) {
            float d = fmaxf(g_deg[gi], 1.0f);
            g_pos[n0 * 3 + t] += g_posdelta[n0 * 3 + t] / d;
        }
    }

    // load FULL n1 weights (both K-halves) + split acts for K=256 (KT=16)
    {
        const uint4* s = (const uint4*)(g_pk_n1 + l * 32768);
        uint4* d = (uint4*)wF;
        for (int i = t; i < 8192; i += 1024) d[i] = s[i];
    }
    for (int i = t; i < 8192; i += 1024) {
        int n = i >> 7, jp = i & 127;
        int j0 = jp * 2;
        int gi = n0 + n;
        float2 v = make_float2(0.f, 0.f);
        if (gi < N_NODES)
            v = (j0 < 128) ? *(const float2*)&g_h[gi * H + j0]
                           : *(const float2*)&g_agg[gi * H + (j0 - 128)];
        unsigned lo;
        unsigned hi = split2(v.x, v.y, lo);
        int fi = fragAb(n, j0, 16);
        aH[fi] = hi;
        aL[fi] = lo;
    }
    __syncthreads();

    float c0[4] = {0.f, 0.f, 0.f, 0.f}, c1[4] = {0.f, 0.f, 0.f, 0.f};
#pragma unroll
    for (int kt = 0; kt < 16; kt++) {
        int aoff = (((mt * 16 + kt) << 5) + lane) << 2;
        uint4 ah = *(const uint4*)&aH[aoff];
        uint4 al = *(const uint4*)&aL[aoff];
        int hk = kt >> 3, kt8 = kt & 7;
        int bbase = hk * 16384;
        int bi0 = bbase + ((((nt0) * 8 + kt8) << 5) + lane) * 2;
        int bi1 = bbase + ((((nt0 + 1) * 8 + kt8) << 5) + lane) * 2;
        uint2 bh0 = *(const uint2*)&wF[bi0];
        uint2 bl0 = *(const uint2*)&wF[bi0 + 8192];
        uint2 bh1 = *(const uint2*)&wF[bi1];
        uint2 bl1 = *(const uint2*)&wF[bi1 + 8192];
        mma3(c0, ah, al, bh0, bl0);
        mma3(c1, ah, al, bh1, bl1);
    }

    float b00 = __ldg(&b1n[j00]), b01 = __ldg(&b1n[j00 + 1]);
    float b10 = __ldg(&b1n[j10]), b11 = __ldg(&b1n[j10 + 1]);
    float u00 = silu_f(c0[0] + b00), u01 = silu_f(c0[1] + b01);
    float u02 = silu_f(c0[2] + b00), u03 = silu_f(c0[3] + b01);
    float u10 = silu_f(c1[0] + b10), u11 = silu_f(c1[1] + b11);
    float u12 = silu_f(c1[2] + b10), u13 = silu_f(c1[3] + b11);
    __syncthreads();
    {
        unsigned lo;
        unsigned hi;
        int fi;
        hi = split2(u00, u01, lo); fi = fragAb(ee0, j00, 8); aH[fi] = hi; aL[fi] = lo;
        hi = split2(u02, u03, lo); fi = fragAb(ee1, j00, 8); aH[fi] = hi; aL[fi] = lo;
        hi = split2(u10, u11, lo); fi = fragAb(ee0, j10, 8); aH[fi] = hi; aL[fi] = lo;
        hi = split2(u12, u13, lo); fi = fragAb(ee1, j10, 8); aH[fi] = hi; aL[fi] = lo;
    }
    {
        const uint4* s = (const uint4*)(g_pk_n2 + l * 16384);
        uint4* d = (uint4*)wF;
        for (int i = t; i < 4096; i += 1024) d[i] = s[i];
    }
    __syncthreads();

    float d0[4] = {0.f, 0.f, 0.f, 0.f}, d1[4] = {0.f, 0.f, 0.f, 0.f};
#pragma unroll
    for (int kt = 0; kt < 8; kt++) {
        int aoff = (((mt * 8 + kt) << 5) + lane) << 2;
        uint4 ah = *(const uint4*)&aH[aoff];
        uint4 al = *(const uint4*)&aL[aoff];
        int bi0 = (((nt0 * 8 + kt) << 5) + lane) << 1;
        int bi1 = ((((nt0 + 1) * 8 + kt) << 5) + lane) << 1;
        uint2 bh0 = *(const uint2*)&wF[bi0];
        uint2 bl0 = *(const uint2*)&wF[8192 + bi0];
        uint2 bh1 = *(const uint2*)&wF[bi1];
        uint2 bl1 = *(const uint2*)&wF[8192 + bi1];
        mma3(d0, ah, al, bh0, bl0);
        mma3(d1, ah, al, bh1, bl1);
    }
    float e00 = __ldg(&b2n[j00]), e01 = __ldg(&b2n[j00 + 1]);
    float e10 = __ldg(&b2n[j10]), e11 = __ldg(&b2n[j10 + 1]);
    float hn00 = 0.f, hn01 = 0.f, hn02 = 0.f, hn03 = 0.f;
    float hn10 = 0.f, hn11 = 0.f, hn12 = 0.f, hn13 = 0.f;
    if (g0 < N_NODES) {
        float2 h0 = *(float2*)&g_h[g0 * H + j00];
        hn00 = h0.x + d0[0] + e00; hn01 = h0.y + d0[1] + e01;
        *(float2*)&g_h[g0 * H + j00] = make_float2(hn00, hn01);
        float2 h1 = *(float2*)&g_h[g0 * H + j10];
        hn02 = h1.x + d1[0] + e10; hn03 = h1.y + d1[1] + e11;
        *(float2*)&g_h[g0 * H + j10] = make_float2(hn02, hn03);
    }
    if (g1 < N_NODES) {
        float2 h0 = *(float2*)&g_h[g1 * H + j00];
        hn10 = h0.x + d0[2] + e00; hn11 = h0.y + d0[3] + e01;
        *(float2*)&g_h[g1 * H + j00] = make_float2(hn10, hn11);
        float2 h1 = *(float2*)&g_h[g1 * H + j10];
        hn12 = h1.x + d1[2] + e10; hn13 = h1.y + d1[3] + e11;
        *(float2*)&g_h[g1 * H + j10] = make_float2(hn12, hn13);
    }

    if (nextl >= NLAYERS) return;

    // ---- fused proj for layer nextl ----
    __syncthreads();
    {
        unsigned lo;
        unsigned hi;
        int fi;
        hi = split2(hn00, hn01, lo); fi = fragAb(ee0, j00, 8); aH[fi] = hi; aL[fi] = lo;
        hi = split2(hn02, hn03, lo); fi = fragAb(ee0, j10, 8); aH[fi] = hi; aL[fi] = lo;
        hi = split2(hn10, hn11, lo); fi = fragAb(ee1, j00, 8); aH[fi] = hi; aL[fi] = lo;
        hi = split2(hn12, hn13, lo); fi = fragAb(ee1, j10, 8); aH[fi] = hi; aL[fi] = lo;
    }
    {
        const uint4* s = (const uint4*)(g_pk_proj + nextl * 32768);
        uint4* d = (uint4*)wF;
        for (int i = t; i < 8192; i += 1024) d[i] = s[i];
    }
    {
        const float4 z4 = make_float4(0.f, 0.f, 0.f, 0.f);
        for (int i = t; i < 2048; i += 1024) {
            int gi = n0 + (i >> 5);
            if (gi < N_NODES) *(float4*)&g_agg[gi * H + (i & 31) * 4] = z4;
        }
    }
    if (t < 192) {
        int gi = n0 + t / 3;
        if (gi < N_NODES) g_posdelta[gi * 3 + t % 3] = 0.f;
    }
    __syncthreads();

    const int ngp = wid & 7;
    float c[4][4];
#pragma unroll
    for (int q = 0; q < 4; q++)
#pragma unroll
        for (int r = 0; r < 4; r++) c[q][r] = 0.f;
#pragma unroll
    for (int kt = 0; kt < 8; kt++) {
        int aoff = (((mt * 8 + kt) << 5) + lane) << 2;
        uint4 ah = *(const uint4*)&aH[aoff];
        uint4 al = *(const uint4*)&aL[aoff];
#pragma unroll
        for (int q = 0; q < 4; q++) {
            int nt = ngp * 4 + q;
            int bi = (((nt * 8 + kt) << 5) + lane) << 1;
            uint2 bh = *(const uint2*)&wF[bi];
            uint2 bl = *(const uint2*)&wF[16384 + bi];
            mma3(c[q], ah, al, bh, bl);
        }
    }
#pragma unroll
    for (int q = 0; q < 4; q++) {
        int nt = ngp * 4 + q;
        int jj0 = nt * 8 + 2 * thr;
        int half = jj0 >> 7;
        int j = jj0 & 127;
        float* outp = half ? g_P2 : g_P1;
        float bb0 = half ? 0.f : __ldg(&b1next[j]);
        float bb1 = half ? 0.f : __ldg(&b1next[j + 1]);
        if (g0 < N_NODES)
            *(float2*)&outp[g0 * H + j] = make_float2(c[q][0] + bb0, c[q][1] + bb1);
        if (g1 < N_NODES)
            *(float2*)&outp[g1 * H + j] = make_float2(c[q][2] + bb0, c[q][3] + bb1);
    }
}

// ---------------- pooling + readout head fused ----------------
__global__ __launch_bounds__(512) void k_poolhead(
    const float* __restrict__ h1_w, const float* __restrict__ h1_b,
    const float* __restrict__ h2_w, const float* __restrict__ h2_b,
    const float* __restrict__ h3_w, const float* __restrict__ h3_b,
    float* __restrict__ out) {
    __shared__ float red[512], gf[256], z1[128], z2[64];
    const int g = blockIdx.x, t = threadIdx.x;
    const int j = t & 127, w = t >> 7;
    float s = 0.f;
    for (int n = w; n < NPG; n += 4) s += g_h[(g * NPG + n) * H + j];
    red[t] = s;
    __syncthreads();
    if (w == 0) {
        float tot = red[j] + red[128 + j] + red[256 + j] + red[384 + j];
        gf[j] = tot;
        gf[128 + j] = tot * (1.f / (float)NPG);
    }
    __syncthreads();
    if (t < 128) {
        float a = h1_b[t];
        for (int k = 0; k < 256; k++) a += gf[k] * h1_w[k * 128 + t];
        z1[t] = fmaxf(a, 0.f);
    }
    __syncthreads();
    if (t < 64) {
        float a2 = h2_b[t];
        for (int k = 0; k < 128; k++) a2 += z1[k] * h2_w[k * 64 + t];
        z2[t] = fmaxf(a2, 0.f);
    }
    __syncthreads();
    if (t == 0) {
        float a3 = h3_b[0];
        for (int k = 0; k < 64; k++) a3 += z2[k] * h3_w[k];
        out[g] = a3;
    }
}

// ---------------- launch ----------------
extern "C" void kernel_launch(void* const* d_in, const int* in_sizes, int n_in,
                              void* d_out, int out_size) {
    const float* x     = (const float*)d_in[0];
    const float* pos   = (const float*)d_in[1];
    const int*   ei    = (const int*)d_in[2];
    const float* eattr = (const float*)d_in[3];
    const float* Wp    = (const float*)d_in[6];
    const float* bp    = (const float*)d_in[7];
    const float* Wl    = (const float*)d_in[8];
    const float* bl    = (const float*)d_in[9];
    const float* gamma = (const float*)d_in[10];
    const float* beta  = (const float*)d_in[11];
    const float* e_w1  = (const float*)d_in[12];
    const float* e_b1  = (const float*)d_in[13];
    const float* e_w2  = (const float*)d_in[14];
    const float* e_b2  = (const float*)d_in[15];
    const float* c_w1  = (const float*)d_in[16];
    const float* c_b1  = (const float*)d_in[17];
    const float* c_w2  = (const float*)d_in[18];
    const float* n_w1  = (const float*)d_in[19];
    const float* n_b1  = (const float*)d_in[20];
    const float* n_w2  = (const float*)d_in[21];
    const float* n_b2  = (const float*)d_in[22];
    const float* h1_w  = (const float*)d_in[23];
    const float* h1_b  = (const float*)d_in[24];
    const float* h2_w  = (const float*)d_in[25];
    const float* h2_b  = (const float*)d_in[26];
    const float* h3_w  = (const float*)d_in[27];
    const float* h3_b  = (const float*)d_in[28];
    float* out = (float*)d_out;

    const int PROJ_SMEM = (32768 + 4096 + 4096) * 4;
    const int EDGE_SMEM = (16384 * 2 + 8192 * 2 + 128 * 4 + 512
                           + 128 + 384 + 512 + 128 + 128 + 128) * 4;
    const int NODE_SMEM = (32768 + 8192 + 8192) * 4;
    cudaFuncSetAttribute(k_proj0, cudaFuncAttributeMaxDynamicSharedMemorySize, PROJ_SMEM);
    cudaFuncSetAttribute(k_edge, cudaFuncAttributeMaxDynamicSharedMemorySize, EDGE_SMEM);
    cudaFuncSetAttribute(k_node, cudaFuncAttributeMaxDynamicSharedMemorySize, NODE_SMEM);

    k_embed<<<N_NODES, 128>>>(x, pos, Wp, bp, Wl, bl);
    k_prep<<<256 + DEG_BLOCKS + PACK_BLOCKS, 512>>>(ei, e_w1, e_w2, c_w1, n_w1, n_w2);
    k_proj0<<<1 + PERM_BLOCKS + NB64, 1024, PROJ_SMEM>>>(ei, e_b1, gamma, beta);

    for (int l = 0; l < NLAYERS; l++) {
        k_edge<<<148, 1024, EDGE_SMEM>>>(eattr, l, e_b2 + l * H, c_b1 + l * H,
                                         c_w2 + l * H, e_w1 + l * 261 * H);
        int nextl = l + 1;
        const float* b1next = (nextl < NLAYERS) ? (e_b1 + nextl * H) : e_b1;
        k_node<<<NB64, 1024, NODE_SMEM>>>(l, n_b1 + l * H, n_b2 + l * H, nextl, b1next);
    }

    k_poolhead<<<G_GRAPHS, 512>>>(h1_w, h1_b, h2_w, h2_b, h3_w, h3_b, out);
}